// round 16
// baseline (speedup 1.0000x reference)
#include <cuda_runtime.h>
#include <cuda_bf16.h>
#include <math.h>
#include <cstdint>

// Scratch (no cudaMalloc allowed)
__device__ float g_qkv[4L * 2048 * 3072];    // tf32-rounded qkv
__device__ float g_attn[4L * 2048 * 1024];   // tf32-rounded attention out
__device__ float g_xr[8192L * 1024];         // tf32-rounded x
__device__ float g_wqkvr[3072L * 1024];      // tf32-rounded W_qkv
__device__ float g_woutr[1024L * 1024];      // tf32-rounded W_out

// ===========================================================================
// helpers (sm_103 base target only — tcgen05/TMEM unavailable in this devloop)
// ===========================================================================
__device__ __forceinline__ uint32_t smem_to_u32(const void* p) {
    uint32_t a;
    asm("{ .reg .u64 t; cvta.to.shared.u64 t, %1; cvt.u32.u64 %0, t; }"
        : "=r"(a) : "l"(p));
    return a;
}

__device__ __forceinline__ void cp_async16(uint32_t dst, const void* src) {
    asm volatile("cp.async.cg.shared.global [%0], [%1], 16;" :: "r"(dst), "l"(src));
}
#define CP_COMMIT() asm volatile("cp.async.commit_group;" ::: "memory")
#define CP_WAIT(n)  asm volatile("cp.async.wait_group %0;" :: "n"(n) : "memory")

__device__ __forceinline__ uint32_t f2tf32(float f) {
    uint32_t r;
    asm("cvt.rna.tf32.f32 %0, %1;" : "=r"(r) : "f"(f));
    return r;
}

__device__ __forceinline__ void mma_tf32(float* c, const uint32_t* a,
                                         uint32_t b0, uint32_t b1) {
    asm volatile(
        "mma.sync.aligned.m16n8k8.row.col.f32.tf32.tf32.f32 "
        "{%0,%1,%2,%3}, {%4,%5,%6,%7}, {%8,%9}, {%0,%1,%2,%3};"
        : "+f"(c[0]), "+f"(c[1]), "+f"(c[2]), "+f"(c[3])
        : "r"(a[0]), "r"(a[1]), "r"(a[2]), "r"(a[3]), "r"(b0), "r"(b1));
}

// elementwise rna-round to tf32 (float4 per thread)
__global__ __launch_bounds__(256) void round_tf32(const float* __restrict__ in,
                                                  float* __restrict__ out, int n4) {
    int i = blockIdx.x * 256 + threadIdx.x;
    if (i < n4) {
        float4 v = ((const float4*)in)[i];
        v.x = __uint_as_float(f2tf32(v.x));
        v.y = __uint_as_float(f2tf32(v.y));
        v.z = __uint_as_float(f2tf32(v.z));
        v.w = __uint_as_float(f2tf32(v.w));
        ((float4*)out)[i] = v;
    }
}

// ===========================================================================
// tf32 mma.sync GEMM: C[M,N] = A[M,K] * B[N,K]^T ; inputs PRE-ROUNDED to tf32.
// CTA 128x128, BK=32, 256 threads (8 warps, 32m x 64n), THREE-stage cp.async
// pipeline, ONE __syncthreads per k-tile. XOR-row-parity swizzle, all
// fragment gathers are single LDS.128, no cvt anywhere in the loop.
// ===========================================================================
static constexpr int TILE_F = 128 * 32;                  // floats per tile
static constexpr int BUF_F  = 2 * TILE_F;                // A+B per stage
static constexpr int GEMM_SMEM_BYTES = 3 * BUF_F * 4;    // 98304 (3 stages)

template <bool CVT_OUT>
__global__ __launch_bounds__(256, 2) void gemm_mma(const float* __restrict__ A,
                                                   const float* __restrict__ B,
                                                   float* __restrict__ C,
                                                   int M, int N, int K) {
    extern __shared__ float smem[];
    uint32_t sb = smem_to_u32(smem);

    int tid  = threadIdx.x;
    int wid  = tid >> 5;
    int lane = tid & 31;
    int gid  = lane >> 2;
    int tig  = lane & 3;
    int wm   = wid & 3;
    int wn   = wid >> 2;
    int bm   = blockIdx.y * 128;
    int bn   = blockIdx.x * 128;

    const int n_iters = K / 32;

    auto load_tile = [&](int it, int st) {
        uint32_t abase = sb + (uint32_t)st * (BUF_F * 4);
        uint32_t bbase = abase + TILE_F * 4;
        const char* Ab = (const char*)(A + (size_t)bm * K + (size_t)it * 32);
        const char* Bb = (const char*)(B + (size_t)bn * K + (size_t)it * 32);
#pragma unroll
        for (int i = 0; i < 4; i++) {
            int ch  = tid + i * 256;
            int r   = ch >> 3;
            int c16 = (ch & 7) * 16;
            uint32_t sc = (uint32_t)(c16 ^ ((r & 1) << 6));
            cp_async16(abase + r * 128 + sc, Ab + (size_t)r * K * 4 + c16);
            cp_async16(bbase + r * 128 + sc, Bb + (size_t)r * K * 4 + c16);
        }
        CP_COMMIT();
    };

    float acc[2][8][4];
#pragma unroll
    for (int mt = 0; mt < 2; mt++)
#pragma unroll
        for (int nt = 0; nt < 8; nt++)
#pragma unroll
            for (int j = 0; j < 4; j++) acc[mt][nt][j] = 0.f;

    load_tile(0, 0);
    load_tile(1, 1);

    int st = 0;       // stage holding k-tile `it`
    int stn = 2;      // stage to prefetch into
    for (int it = 0; it < n_iters; it++) {
        // retire stage `it` (leave the newer prefetch pending)
        if (it + 1 < n_iters) { CP_WAIT(1); } else { CP_WAIT(0); }
        __syncthreads();                       // the ONLY barrier per k-tile
        if (it + 2 < n_iters) load_tile(it + 2, stn);

        const float4* As4 = (const float4*)(smem + st * BUF_F);
        const float4* Bs4 = As4 + TILE_F / 4;

#pragma unroll
        for (int p = 0; p < 2; p++) {
            uint32_t a0[2][4], a1[2][4];
#pragma unroll
            for (int mt = 0; mt < 2; mt++) {
                int r = wm * 32 + mt * 16 + gid;
                int q = (p * 4 + tig) ^ ((r & 1) << 2);
                float4 lo = As4[r * 8 + q];
                float4 hi = As4[(r + 8) * 8 + q];
                a0[mt][0] = __float_as_uint(lo.x); a0[mt][1] = __float_as_uint(hi.x);
                a0[mt][2] = __float_as_uint(lo.y); a0[mt][3] = __float_as_uint(hi.y);
                a1[mt][0] = __float_as_uint(lo.z); a1[mt][1] = __float_as_uint(hi.z);
                a1[mt][2] = __float_as_uint(lo.w); a1[mt][3] = __float_as_uint(hi.w);
            }
#pragma unroll
            for (int nt = 0; nt < 8; nt++) {
                int rn = wn * 64 + nt * 8 + gid;
                int q  = (p * 4 + tig) ^ ((rn & 1) << 2);
                float4 bv = Bs4[rn * 8 + q];
                uint32_t b0 = __float_as_uint(bv.x), b1 = __float_as_uint(bv.y);
                uint32_t b2 = __float_as_uint(bv.z), b3 = __float_as_uint(bv.w);
                mma_tf32(acc[0][nt], a0[0], b0, b1);
                mma_tf32(acc[1][nt], a0[1], b0, b1);
                mma_tf32(acc[0][nt], a1[0], b2, b3);
                mma_tf32(acc[1][nt], a1[1], b2, b3);
            }
        }
        st = (st == 2) ? 0 : st + 1;
        stn = (stn == 2) ? 0 : stn + 1;
    }

#pragma unroll
    for (int mt = 0; mt < 2; mt++) {
        int row = bm + wm * 32 + mt * 16 + gid;
#pragma unroll
        for (int nt = 0; nt < 8; nt++) {
            int col = bn + wn * 64 + nt * 8 + tig * 2;
            float v0 = acc[mt][nt][0], v1 = acc[mt][nt][1];
            float v2 = acc[mt][nt][2], v3 = acc[mt][nt][3];
            if (CVT_OUT) {
                v0 = __uint_as_float(f2tf32(v0));
                v1 = __uint_as_float(f2tf32(v1));
                v2 = __uint_as_float(f2tf32(v2));
                v3 = __uint_as_float(f2tf32(v3));
            }
            *(float2*)&C[(size_t)row * N + col] = make_float2(v0, v1);
            *(float2*)&C[(size_t)(row + 8) * N + col] = make_float2(v2, v3);
        }
    }
}

// ===========================================================================
// Causal flash attention, tf32 mma.sync, hd=64, DOUBLE-BUFFERED K/V.
// Block: 128 q-rows x (b,h); 8 warps, warp owns 16 q-rows. K-tiles of 64.
// smem: QP[128][68] + K0/K1/V0/V1 [64][68] = 104448 B (2 CTAs/SM).
// ===========================================================================
static constexpr int APAD = 68;
static constexpr int ATT_QP_F = 128 * APAD;
static constexpr int ATT_K_F  = 64 * APAD;
static constexpr int ATT_SMEM_BYTES = (ATT_QP_F + 4 * ATT_K_F) * 4;   // 104448

__global__ __launch_bounds__(256, 2) void attn_mma(const float* __restrict__ qkv,
                                                   float* __restrict__ attn) {
    const int S = 2048, TD = 3072, D = 1024;
    extern __shared__ float sm[];
    float* QP = sm;                                   // [128][68]: Q then P
    const uint32_t* QPu = (const uint32_t*)QP;

    uint32_t sb = smem_to_u32(sm);

    int tid  = threadIdx.x;
    int wid  = tid >> 5;
    int lane = tid & 31;
    int gid  = lane >> 2;
    int tig  = lane & 3;
    int qt = blockIdx.x, h = blockIdx.y, b = blockIdx.z;
    int qbase = qt * 128;
    int r0 = wid * 16 + gid;

    const char* Kg0 = (const char*)(qkv + (size_t)(b * S) * TD + 1024 + h * 64);
    const char* Vg0 = (const char*)(qkv + (size_t)(b * S) * TD + 2048 + h * 64);

    auto load_kv = [&](int kt, int buf) {
        uint32_t kbase = sb + (ATT_QP_F + buf * ATT_K_F) * 4;
        uint32_t vbase = sb + (ATT_QP_F + (2 + buf) * ATT_K_F) * 4;
        size_t off = (size_t)(kt * 64) * TD * 4;
#pragma unroll
        for (int i = 0; i < 4; i++) {
            int ch  = tid + i * 256;
            int r   = ch >> 4;
            int c16 = (ch & 15) * 16;
            cp_async16(kbase + r * (APAD * 4) + c16,
                       Kg0 + off + (size_t)r * TD * 4 + c16);
            cp_async16(vbase + r * (APAD * 4) + c16,
                       Vg0 + off + (size_t)r * TD * 4 + c16);
        }
        CP_COMMIT();
    };

    // ---- issue Q load, then KV(0); wait only for Q ----
    {
        const char* Qg = (const char*)(qkv + (size_t)(b * S + qbase) * TD + h * 64);
#pragma unroll
        for (int i = 0; i < 8; i++) {
            int ch  = tid + i * 256;
            int r   = ch >> 4;
            int c16 = (ch & 15) * 16;
            cp_async16(sb + r * (APAD * 4) + c16, Qg + (size_t)r * TD * 4 + c16);
        }
        CP_COMMIT();
    }
    load_kv(0, 0);
    CP_WAIT(1);                // Q group retired; KV(0) still in flight
    __syncthreads();

    // ---- Q fragments (scale 1/8 folded; exact on tf32) ----
    uint32_t qa[8][4];
#pragma unroll
    for (int ks = 0; ks < 8; ks++) {
        int kc = ks * 8 + tig;
        qa[ks][0] = __float_as_uint(0.125f * QP[r0 * APAD + kc]);
        qa[ks][1] = __float_as_uint(0.125f * QP[(r0 + 8) * APAD + kc]);
        qa[ks][2] = __float_as_uint(0.125f * QP[r0 * APAD + kc + 4]);
        qa[ks][3] = __float_as_uint(0.125f * QP[(r0 + 8) * APAD + kc + 4]);
    }
    // (no barrier: P writes below touch only this warp's own QP rows)

    float oa[8][4];
#pragma unroll
    for (int nt = 0; nt < 8; nt++)
#pragma unroll
        for (int j = 0; j < 4; j++) oa[nt][j] = 0.f;
    float m0 = -1e30f, m1 = -1e30f, l0 = 0.f, l1 = 0.f;

    const int qg0 = qbase + r0;
    const int qg1 = qg0 + 8;
    const int ktmax = 2 * qt + 1;

    for (int kt = 0; kt <= ktmax; kt++) {
        int buf = kt & 1;
        // prefetch next tile into the other buffer, then retire this tile
        if (kt + 1 <= ktmax) {
            load_kv(kt + 1, buf ^ 1);
            CP_WAIT(1);
        } else {
            CP_WAIT(0);
        }
        __syncthreads();

        const uint32_t* Ksu =
            (const uint32_t*)(sm + ATT_QP_F + buf * ATT_K_F);
        const uint32_t* Vsu =
            (const uint32_t*)(sm + ATT_QP_F + (2 + buf) * ATT_K_F);

        // ---- S = (Q/8) K^T : warp 16x64 ----
        float sa[8][4];
#pragma unroll
        for (int nt = 0; nt < 8; nt++)
#pragma unroll
            for (int j = 0; j < 4; j++) sa[nt][j] = 0.f;
#pragma unroll
        for (int ks = 0; ks < 8; ks++) {
            int kc = ks * 8 + tig;
#pragma unroll
            for (int nt = 0; nt < 8; nt++) {
                int rn = nt * 8 + gid;
                uint32_t b0 = Ksu[rn * APAD + kc];
                uint32_t b1 = Ksu[rn * APAD + kc + 4];
                mma_tf32(sa[nt], qa[ks], b0, b1);
            }
        }

        if (kt >= 2 * qt) {
#pragma unroll
            for (int nt = 0; nt < 8; nt++) {
                int kg = kt * 64 + nt * 8 + tig * 2;
                if (kg > qg0)     sa[nt][0] = -1e30f;
                if (kg + 1 > qg0) sa[nt][1] = -1e30f;
                if (kg > qg1)     sa[nt][2] = -1e30f;
                if (kg + 1 > qg1) sa[nt][3] = -1e30f;
            }
        }

        // ---- online softmax (rows r0, r0+8) ----
        float v0 = -1e30f, v1 = -1e30f;
#pragma unroll
        for (int nt = 0; nt < 8; nt++) {
            v0 = fmaxf(v0, fmaxf(sa[nt][0], sa[nt][1]));
            v1 = fmaxf(v1, fmaxf(sa[nt][2], sa[nt][3]));
        }
        v0 = fmaxf(v0, __shfl_xor_sync(0xffffffff, v0, 1));
        v0 = fmaxf(v0, __shfl_xor_sync(0xffffffff, v0, 2));
        v1 = fmaxf(v1, __shfl_xor_sync(0xffffffff, v1, 1));
        v1 = fmaxf(v1, __shfl_xor_sync(0xffffffff, v1, 2));
        float mn0 = fmaxf(m0, v0), mn1 = fmaxf(m1, v1);
        float f0 = __expf(m0 - mn0), f1 = __expf(m1 - mn1);
        m0 = mn0; m1 = mn1;

        float ls0 = 0.f, ls1 = 0.f;
#pragma unroll
        for (int nt = 0; nt < 8; nt++) {
            int col = nt * 8 + tig * 2;
            float p00 = __expf(sa[nt][0] - mn0);
            float p01 = __expf(sa[nt][1] - mn0);
            float p10 = __expf(sa[nt][2] - mn1);
            float p11 = __expf(sa[nt][3] - mn1);
            ls0 += p00 + p01;
            ls1 += p10 + p11;
            QP[r0 * APAD + col]       = __uint_as_float(f2tf32(p00));
            QP[r0 * APAD + col + 1]   = __uint_as_float(f2tf32(p01));
            QP[(r0 + 8) * APAD + col]     = __uint_as_float(f2tf32(p10));
            QP[(r0 + 8) * APAD + col + 1] = __uint_as_float(f2tf32(p11));
        }
        l0 = l0 * f0 + ls0;
        l1 = l1 * f1 + ls1;
#pragma unroll
        for (int nt = 0; nt < 8; nt++) {
            oa[nt][0] *= f0; oa[nt][1] *= f0;
            oa[nt][2] *= f1; oa[nt][3] *= f1;
        }
        __syncwarp();

        // ---- O += P V ----
#pragma unroll
        for (int ks = 0; ks < 8; ks++) {
            int kc = ks * 8 + tig;
            uint32_t pa[4];
            pa[0] = QPu[r0 * APAD + kc];
            pa[1] = QPu[(r0 + 8) * APAD + kc];
            pa[2] = QPu[r0 * APAD + kc + 4];
            pa[3] = QPu[(r0 + 8) * APAD + kc + 4];
#pragma unroll
            for (int nt = 0; nt < 8; nt++) {
                int rn = nt * 8 + gid;
                uint32_t b0 = Vsu[kc * APAD + rn];
                uint32_t b1 = Vsu[(kc + 4) * APAD + rn];
                mma_tf32(oa[nt], pa, b0, b1);
            }
        }
        __syncthreads();   // all warps done with this KV buffer (overwritten kt+2)
    }

    l0 += __shfl_xor_sync(0xffffffff, l0, 1);
    l0 += __shfl_xor_sync(0xffffffff, l0, 2);
    l1 += __shfl_xor_sync(0xffffffff, l1, 1);
    l1 += __shfl_xor_sync(0xffffffff, l1, 2);
    float inv0 = 1.f / l0, inv1 = 1.f / l1;

    size_t row0 = (size_t)(b * S + qbase + r0);
#pragma unroll
    for (int nt = 0; nt < 8; nt++) {
        int col = h * 64 + nt * 8 + tig * 2;
        *(float2*)&attn[row0 * D + col] = make_float2(
            __uint_as_float(f2tf32(oa[nt][0] * inv0)),
            __uint_as_float(f2tf32(oa[nt][1] * inv0)));
        *(float2*)&attn[(row0 + 8) * D + col] = make_float2(
            __uint_as_float(f2tf32(oa[nt][2] * inv1)),
            __uint_as_float(f2tf32(oa[nt][3] * inv1)));
    }
}

extern "C" void kernel_launch(void* const* d_in, const int* in_sizes, int n_in,
                              void* d_out, int out_size) {
    const float* x    = (const float*)d_in[0];   // [4,2048,1024]
    const float* Wqkv = (const float*)d_in[1];   // [3072,1024]
    const float* Wout = (const float*)d_in[2];   // [1024,1024]
    float* out = (float*)d_out;                  // [4,2048,1024]

    float *qkv, *attn, *xr, *wqkvr, *woutr;
    cudaGetSymbolAddress((void**)&qkv, g_qkv);
    cudaGetSymbolAddress((void**)&attn, g_attn);
    cudaGetSymbolAddress((void**)&xr, g_xr);
    cudaGetSymbolAddress((void**)&wqkvr, g_wqkvr);
    cudaGetSymbolAddress((void**)&woutr, g_woutr);

    cudaFuncSetAttribute(gemm_mma<true>, cudaFuncAttributeMaxDynamicSharedMemorySize,
                         GEMM_SMEM_BYTES);
    cudaFuncSetAttribute(gemm_mma<false>, cudaFuncAttributeMaxDynamicSharedMemorySize,
                         GEMM_SMEM_BYTES);
    cudaFuncSetAttribute(attn_mma, cudaFuncAttributeMaxDynamicSharedMemorySize,
                         ATT_SMEM_BYTES);

    // pre-round inputs to tf32 (rna) once
    round_tf32<<<(8192 * 1024 / 4 + 255) / 256, 256>>>(x, xr, 8192 * 1024 / 4);
    round_tf32<<<(3072 * 1024 / 4 + 255) / 256, 256>>>(Wqkv, wqkvr, 3072 * 1024 / 4);
    round_tf32<<<(1024 * 1024 / 4 + 255) / 256, 256>>>(Wout, woutr, 1024 * 1024 / 4);

    // qkv = x @ Wqkv^T (tf32 out for attention raw loads)
    gemm_mma<true><<<dim3(3072 / 128, 8192 / 128), 256, GEMM_SMEM_BYTES>>>(
        xr, wqkvr, qkv, 8192, 3072, 1024);
    // causal MHA
    attn_mma<<<dim3(16, 16, 4), 256, ATT_SMEM_BYTES>>>(qkv, attn);
    // out = attn @ Wout^T (fp32 out)
    gemm_mma<false><<<dim3(1024 / 128, 8192 / 128), 256, GEMM_SMEM_BYTES>>>(
        attn, woutr, out, 8192, 1024, 1024);
}